// round 10
// baseline (speedup 1.0000x reference)
#include <cuda_runtime.h>
#include <cuda_bf16.h>
#include <cstdint>
#include <math.h>

typedef unsigned int u32;
typedef unsigned long long u64;

// Problem constants
#define B_  4
#define L_  1024
#define E_  2048
#define H_  16
#define D_  128
#define BL_ (B_*L_)            // 4096
#define BH_ (B_*H_)            // 64
#define SCALE_ 0.08838834764831845f   // 1/sqrt(128)

// -------- scratch (device globals; no allocation allowed) --------
__device__ float g_Q[(u64)BL_*E_];
__device__ float g_K[(u64)BL_*E_];
__device__ float g_V[(u64)BL_*E_];
__device__ float g_O[(u64)BL_*E_];
__device__ float g_S[(u64)BH_*L_*L_];            // 256MB scores
__device__ __nv_bfloat16 g_Ahi[(u64)BL_*E_];
__device__ __nv_bfloat16 g_Alo[(u64)BL_*E_];
__device__ __nv_bfloat16 g_Whi[(u64)E_*E_];
__device__ __nv_bfloat16 g_Wlo[(u64)E_*E_];
__device__ __nv_bfloat16 g_Qhi[(u64)BH_*L_*D_];  // [bh][l][d]
__device__ __nv_bfloat16 g_Qlo[(u64)BH_*L_*D_];
__device__ __nv_bfloat16 g_Khi[(u64)BH_*L_*D_];
__device__ __nv_bfloat16 g_Klo[(u64)BH_*L_*D_];
__device__ __nv_bfloat16 g_Vthi[(u64)BH_*D_*L_]; // [bh][d][l]
__device__ __nv_bfloat16 g_Vtlo[(u64)BH_*D_*L_];
__device__ __nv_bfloat16 g_Phi[(u64)BH_*L_*L_];  // [bh][i][j]
__device__ __nv_bfloat16 g_Plo[(u64)BH_*L_*L_];

// ============================================================================
// helpers
// ============================================================================
__device__ __forceinline__ void cp16(u32 dst, const void* src) {
    asm volatile("cp.async.cg.shared.global [%0], [%1], 16;" :: "r"(dst), "l"(src) : "memory");
}

__device__ __forceinline__ void mma_bf16(float* d, const u32* a, const u32* b) {
    asm volatile(
        "mma.sync.aligned.m16n8k16.row.col.f32.bf16.bf16.f32 "
        "{%0,%1,%2,%3}, {%4,%5,%6,%7}, {%8,%9}, {%0,%1,%2,%3};"
        : "+f"(d[0]), "+f"(d[1]), "+f"(d[2]), "+f"(d[3])
        : "r"(a[0]), "r"(a[1]), "r"(a[2]), "r"(a[3]), "r"(b[0]), "r"(b[1]));
}

__device__ __forceinline__ void ldsm_x4(u32* r, u32 addr) {
    asm volatile("ldmatrix.sync.aligned.m8n8.x4.shared.b16 {%0,%1,%2,%3}, [%4];"
        : "=r"(r[0]), "=r"(r[1]), "=r"(r[2]), "=r"(r[3]) : "r"(addr));
}

__device__ __forceinline__ void split1(float v, unsigned short& h, unsigned short& l) {
    __nv_bfloat16 hb = __float2bfloat16(v);
    __nv_bfloat16 lb = __float2bfloat16(v - __bfloat162float(hb));
    h = __bfloat16_as_ushort(hb);
    l = __bfloat16_as_ushort(lb);
}

// ============================================================================
// Split fp32 -> bf16 hi + bf16 lo
// ============================================================================
__global__ __launch_bounds__(256) void split_kernel(
    const float* __restrict__ X, __nv_bfloat16* __restrict__ hi,
    __nv_bfloat16* __restrict__ lo, int n)
{
    int i = (blockIdx.x * 256 + threadIdx.x) * 4;
    if (i >= n) return;
    float4 x = *(const float4*)(X + i);
    float v[4] = {x.x, x.y, x.z, x.w};
    unsigned short hv[4], lv[4];
    #pragma unroll
    for (int k = 0; k < 4; k++) split1(v[k], hv[k], lv[k]);
    *(ushort4*)(hi + i) = make_ushort4(hv[0], hv[1], hv[2], hv[3]);
    *(ushort4*)(lo + i) = make_ushort4(lv[0], lv[1], lv[2], lv[3]);
}

// ============================================================================
// Projection GEMM: C = A @ B^T + bias. ldmatrix for fragments (ONLY change
// vs the R8 known-good kernel; B fragments consumed per 16-row group to keep
// register pressure at R8 levels).
// ============================================================================
#define GM_M 4096
#define GM_N 2048
#define GM_K 2048
#define BKH 32
#define ROWP 40
#define T_ALO_H 5120
#define T_BHI_H 10240
#define T_BLO_H 15360
#define STAGEH 20480
#define NCH (GM_K / BKH)
#define SMEM_GEMM_BYTES (2 * STAGEH * 2)   // 81920

__device__ __forceinline__ void g_load_stage(
    u32 sbase, int s, int m0, int n0, int k0, int tid,
    const __nv_bfloat16* __restrict__ Ahi, const __nv_bfloat16* __restrict__ Alo,
    const __nv_bfloat16* __restrict__ Bhi, const __nv_bfloat16* __restrict__ Blo)
{
    u32 st = sbase + (u32)s * (STAGEH * 2);
    #pragma unroll
    for (int i = 0; i < 2; ++i) {
        int id = tid + i * 256;
        int r = id >> 2, sg = id & 3;
        u32 doff = (u32)(r * ROWP + sg * 8) * 2;
        u64 ao = (u64)(m0 + r) * GM_K + k0 + sg * 8;
        u64 bo = (u64)(n0 + r) * GM_K + k0 + sg * 8;
        cp16(st + doff, Ahi + ao);
        cp16(st + T_ALO_H * 2 + doff, Alo + ao);
        cp16(st + T_BHI_H * 2 + doff, Bhi + bo);
        cp16(st + T_BLO_H * 2 + doff, Blo + bo);
    }
    asm volatile("cp.async.commit_group;" ::: "memory");
}

__global__ __launch_bounds__(256) void gemm_mma_kernel(
    const __nv_bfloat16* __restrict__ Ahi, const __nv_bfloat16* __restrict__ Alo,
    const __nv_bfloat16* __restrict__ Bhi, const __nv_bfloat16* __restrict__ Blo,
    const float* __restrict__ bias, float* __restrict__ C)
{
    extern __shared__ __align__(16) __nv_bfloat16 sh[];
    const int tid = threadIdx.x;
    const int m0 = blockIdx.y * 128;
    const int n0 = blockIdx.x * 128;
    const int warp = tid >> 5, lane = tid & 31;
    const int wm = warp & 3, wn = warp >> 2;
    const u32 sbase = (u32)__cvta_generic_to_shared(sh);

    float acc[2][8][4];
    #pragma unroll
    for (int i = 0; i < 2; i++)
        #pragma unroll
        for (int j = 0; j < 8; j++)
            #pragma unroll
            for (int k = 0; k < 4; k++) acc[i][j][k] = 0.f;

    g_load_stage(sbase, 0, m0, n0, 0,   tid, Ahi, Alo, Bhi, Blo);
    g_load_stage(sbase, 1, m0, n0, BKH, tid, Ahi, Alo, Bhi, Blo);

    const int fr = lane >> 2;
    const int fc = (lane & 3) * 2;
    // ldmatrix per-thread row-address offset (shared by A and B tiles)
    const int lr = lane & 7;
    const int grow = (lane >> 3) & 1;
    const int gcol = lane >> 4;
    const u32 foff = (u32)(((lr + grow * 8) * ROWP + gcol * 8) * 2);

    for (int c = 0; c < NCH; ++c) {
        const int s = c & 1;
        if (c < NCH - 1) asm volatile("cp.async.wait_group 1;" ::: "memory");
        else             asm volatile("cp.async.wait_group 0;" ::: "memory");
        __syncthreads();

        const u32 stg = sbase + (u32)s * (STAGEH * 2);
        const u32 aH = stg + (u32)(wm * 32 * ROWP) * 2 + foff;
        const u32 aL = aH + T_ALO_H * 2;
        const u32 bB = stg + T_BHI_H * 2 + (u32)(wn * 64 * ROWP) * 2 + foff;
        const u32 bL = bB + (T_BLO_H - T_BHI_H) * 2;

        #pragma unroll
        for (int kk = 0; kk < BKH; kk += 16) {
            u32 fah[2][4], fal[2][4];
            #pragma unroll
            for (int mt = 0; mt < 2; ++mt) {
                ldsm_x4(fah[mt], aH + (u32)(mt * 16 * ROWP + kk) * 2);
                ldsm_x4(fal[mt], aL + (u32)(mt * 16 * ROWP + kk) * 2);
            }
            #pragma unroll
            for (int ntp = 0; ntp < 4; ++ntp) {
                u32 th[4], tl[4];
                ldsm_x4(th, bB + (u32)(ntp * 16 * ROWP + kk) * 2);
                ldsm_x4(tl, bL + (u32)(ntp * 16 * ROWP + kk) * 2);
                u32 b0h[2] = {th[0], th[2]}, b1h[2] = {th[1], th[3]};
                u32 b0l[2] = {tl[0], tl[2]}, b1l[2] = {tl[1], tl[3]};
                #pragma unroll
                for (int mt = 0; mt < 2; ++mt) {
                    mma_bf16(acc[mt][2*ntp], fah[mt], b0h);
                    mma_bf16(acc[mt][2*ntp], fah[mt], b0l);
                    mma_bf16(acc[mt][2*ntp], fal[mt], b0h);
                }
                #pragma unroll
                for (int mt = 0; mt < 2; ++mt) {
                    mma_bf16(acc[mt][2*ntp+1], fah[mt], b1h);
                    mma_bf16(acc[mt][2*ntp+1], fah[mt], b1l);
                    mma_bf16(acc[mt][2*ntp+1], fal[mt], b1h);
                }
            }
        }
        __syncthreads();
        if (c + 2 < NCH)
            g_load_stage(sbase, s, m0, n0, (c + 2) * BKH, tid, Ahi, Alo, Bhi, Blo);
    }

    #pragma unroll
    for (int mt = 0; mt < 2; ++mt) {
        #pragma unroll
        for (int nt = 0; nt < 8; ++nt) {
            int m = m0 + wm * 32 + mt * 16 + fr;
            int n = n0 + wn * 64 + nt * 8 + fc;
            float b0 = bias[n], b1 = bias[n + 1];
            float2 v0 = make_float2(acc[mt][nt][0] + b0, acc[mt][nt][1] + b1);
            float2 v1 = make_float2(acc[mt][nt][2] + b0, acc[mt][nt][3] + b1);
            *(float2*)(C + (u64)m * GM_N + n) = v0;
            *(float2*)(C + (u64)(m + 8) * GM_N + n) = v1;
        }
    }
}

// ============================================================================
// RMSNorm + rotary -> bf16 hi/lo [bh][l][d]   (R8 known-good)
// ============================================================================
__global__ __launch_bounds__(256) void normrope_kernel(
    const float* __restrict__ Q, const float* __restrict__ Kb,
    __nv_bfloat16* __restrict__ Qhi, __nv_bfloat16* __restrict__ Qlo,
    __nv_bfloat16* __restrict__ Khi, __nv_bfloat16* __restrict__ Klo,
    const float* __restrict__ cosp, const float* __restrict__ sinp)
{
    int gw = blockIdx.x * 8 + (threadIdx.x >> 5);
    int lane = threadIdx.x & 31;
    bool isQ = (gw < BL_ * H_);
    const float* X = isQ ? Q : Kb;
    __nv_bfloat16* OH = isQ ? Qhi : Khi;
    __nv_bfloat16* OL = isQ ? Qlo : Klo;
    int w = gw % (BL_ * H_);
    int row = w / H_;
    int h   = w % H_;
    int b   = row >> 10;
    int l   = row & (L_ - 1);
    const float* x = X + (u64)row * E_ + h * D_;

    float v0 = x[lane], v1 = x[lane+32], v2 = x[lane+64], v3 = x[lane+96];
    float ss = v0*v0 + v1*v1 + v2*v2 + v3*v3;
    #pragma unroll
    for (int o = 16; o; o >>= 1) ss += __shfl_xor_sync(0xffffffffu, ss, o);
    float r = rsqrtf(ss * (1.0f / 128.0f) + 1e-6f);
    v0 *= r; v1 *= r; v2 *= r; v3 *= r;

    float c0 = cosp[l*64 + lane],      s0 = sinp[l*64 + lane];
    float c1 = cosp[l*64 + lane + 32], s1 = sinp[l*64 + lane + 32];
    float y0 = v0 * c0 - v2 * s0;
    float y2 = v0 * s0 + v2 * c0;
    float y1 = v1 * c1 - v3 * s1;
    float y3 = v1 * s1 + v3 * c1;

    u64 base = ((u64)(b * H_ + h) * L_ + l) * D_;
    unsigned short hh, ll;
    split1(y0, hh, ll); OH[base + lane]      = __ushort_as_bfloat16(hh); OL[base + lane]      = __ushort_as_bfloat16(ll);
    split1(y1, hh, ll); OH[base + lane + 32] = __ushort_as_bfloat16(hh); OL[base + lane + 32] = __ushort_as_bfloat16(ll);
    split1(y2, hh, ll); OH[base + lane + 64] = __ushort_as_bfloat16(hh); OL[base + lane + 64] = __ushort_as_bfloat16(ll);
    split1(y3, hh, ll); OH[base + lane + 96] = __ushort_as_bfloat16(hh); OL[base + lane + 96] = __ushort_as_bfloat16(ll);
}

// ============================================================================
// V transpose+split -> [bh][d][l] hi/lo   (R8 known-good)
// ============================================================================
__global__ __launch_bounds__(256) void vsplit_kernel(
    const float* __restrict__ V,
    __nv_bfloat16* __restrict__ Vthi, __nv_bfloat16* __restrict__ Vtlo)
{
    __shared__ float tile[32][132];
    const int bh = blockIdx.x;
    const int l0 = blockIdx.y * 32;
    const int b = bh >> 4, h = bh & 15;
    const int tid = threadIdx.x;

    #pragma unroll
    for (int i = 0; i < 16; ++i) {
        int id = tid + i * 256;
        int l = id >> 7, d = id & 127;
        tile[l][d] = V[((u64)(b * L_ + l0 + l)) * E_ + h * D_ + d];
    }
    __syncthreads();
    #pragma unroll
    for (int i = 0; i < 16; ++i) {
        int id = tid + i * 256;
        int d = id >> 5, l = id & 31;
        float v = tile[l][d];
        unsigned short hh, ll;
        split1(v, hh, ll);
        u64 o = ((u64)bh * D_ + d) * L_ + l0 + l;
        Vthi[o] = __ushort_as_bfloat16(hh);
        Vtlo[o] = __ushort_as_bfloat16(ll);
    }
}

// ============================================================================
// scores mma: EXACT R8 known-good version (scalar fragment loads)
// ============================================================================
#define SROWP 136
#define STILE_H (128 * SROWP)
#define SMEM_SC_BYTES (4 * STILE_H * 2)     // 139264

__global__ __launch_bounds__(256) void scores_mma_kernel(
    const __nv_bfloat16* __restrict__ Qhi, const __nv_bfloat16* __restrict__ Qlo,
    const __nv_bfloat16* __restrict__ Khi, const __nv_bfloat16* __restrict__ Klo,
    float* __restrict__ S)
{
    const int j0 = blockIdx.x * 128;
    const int i0 = blockIdx.y * 128;
    if (j0 > i0) return;
    const int bh = blockIdx.z;

    extern __shared__ __align__(16) __nv_bfloat16 sh[];
    const u32 sbase = (u32)__cvta_generic_to_shared(sh);
    const int tid = threadIdx.x;
    const int warp = tid >> 5, lane = tid & 31;
    const int wm = warp & 3, wn = warp >> 2;

    #pragma unroll
    for (int i = 0; i < 8; ++i) {
        int id = tid + i * 256;
        int r = id >> 4, sg = id & 15;
        u32 doff = (u32)(r * SROWP + sg * 8) * 2;
        u64 qo = ((u64)bh * L_ + i0 + r) * D_ + sg * 8;
        u64 ko = ((u64)bh * L_ + j0 + r) * D_ + sg * 8;
        cp16(sbase + doff, Qhi + qo);
        cp16(sbase + STILE_H * 2 + doff, Qlo + qo);
        cp16(sbase + STILE_H * 4 + doff, Khi + ko);
        cp16(sbase + STILE_H * 6 + doff, Klo + ko);
    }
    asm volatile("cp.async.commit_group;" ::: "memory");

    float acc[2][8][4];
    #pragma unroll
    for (int i = 0; i < 2; i++)
        #pragma unroll
        for (int j = 0; j < 8; j++)
            #pragma unroll
            for (int k = 0; k < 4; k++) acc[i][j][k] = 0.f;

    asm volatile("cp.async.wait_group 0;" ::: "memory");
    __syncthreads();

    const int fr = lane >> 2;
    const int fc = (lane & 3) * 2;
    const __nv_bfloat16* aH = sh + (wm * 32 + fr) * SROWP + fc;
    const __nv_bfloat16* aL = aH + STILE_H;
    const __nv_bfloat16* bH = sh + 2 * STILE_H + (wn * 64 + fr) * SROWP + fc;
    const __nv_bfloat16* bL = bH + STILE_H;

    #pragma unroll
    for (int kk = 0; kk < 128; kk += 16) {
        u32 fah[2][4], fal[2][4];
        #pragma unroll
        for (int mt = 0; mt < 2; ++mt) {
            const __nv_bfloat16* p = aH + mt * 16 * SROWP + kk;
            fah[mt][0] = *(const u32*)(p);
            fah[mt][1] = *(const u32*)(p + 8 * SROWP);
            fah[mt][2] = *(const u32*)(p + 8);
            fah[mt][3] = *(const u32*)(p + 8 * SROWP + 8);
            const __nv_bfloat16* q = aL + mt * 16 * SROWP + kk;
            fal[mt][0] = *(const u32*)(q);
            fal[mt][1] = *(const u32*)(q + 8 * SROWP);
            fal[mt][2] = *(const u32*)(q + 8);
            fal[mt][3] = *(const u32*)(q + 8 * SROWP + 8);
        }
        #pragma unroll
        for (int nt = 0; nt < 8; ++nt) {
            u32 fbh[2], fbl[2];
            const __nv_bfloat16* p = bH + nt * 8 * SROWP + kk;
            fbh[0] = *(const u32*)(p);
            fbh[1] = *(const u32*)(p + 8);
            const __nv_bfloat16* q = bL + nt * 8 * SROWP + kk;
            fbl[0] = *(const u32*)(q);
            fbl[1] = *(const u32*)(q + 8);
            #pragma unroll
            for (int mt = 0; mt < 2; ++mt) {
                mma_bf16(acc[mt][nt], fah[mt], fbh);
                mma_bf16(acc[mt][nt], fah[mt], fbl);
                mma_bf16(acc[mt][nt], fal[mt], fbh);
            }
        }
    }

    float* Sh = S + (u64)bh * L_ * L_;
    #pragma unroll
    for (int mt = 0; mt < 2; ++mt) {
        #pragma unroll
        for (int nt = 0; nt < 8; ++nt) {
            int m = i0 + wm * 32 + mt * 16 + fr;
            int n = j0 + wn * 64 + nt * 8 + fc;
            float2 v0 = make_float2(acc[mt][nt][0] * SCALE_, acc[mt][nt][1] * SCALE_);
            float2 v1 = make_float2(acc[mt][nt][2] * SCALE_, acc[mt][nt][3] * SCALE_);
            *(float2*)(Sh + (u64)m * L_ + n) = v0;
            *(float2*)(Sh + (u64)(m + 8) * L_ + n) = v1;
        }
    }
}

// ============================================================================
// Causal softmax -> bf16 hi/lo P   (R8 known-good)
// ============================================================================
__global__ __launch_bounds__(256) void softmax_kernel(
    const float* __restrict__ S,
    __nv_bfloat16* __restrict__ Phi, __nv_bfloat16* __restrict__ Plo)
{
    const int row = blockIdx.x;
    const int i = row & (L_ - 1);
    const int n = i + 1;
    const float* Sr = S + (u64)row * L_;
    __nv_bfloat16* PH = Phi + (u64)row * L_;
    __nv_bfloat16* PL = Plo + (u64)row * L_;
    const int tid = threadIdx.x;
    const int lane = tid & 31, wid = tid >> 5;
    __shared__ float red[8];

    float pm = -3.0e38f;
    for (int j = tid; j < n; j += 256) pm = fmaxf(pm, Sr[j]);
    #pragma unroll
    for (int o = 16; o; o >>= 1) pm = fmaxf(pm, __shfl_xor_sync(0xffffffffu, pm, o));
    if (lane == 0) red[wid] = pm;
    __syncthreads();
    if (tid == 0) {
        float m = red[0];
        #pragma unroll
        for (int k = 1; k < 8; k++) m = fmaxf(m, red[k]);
        red[0] = m;
    }
    __syncthreads();
    const float m = red[0];
    __syncthreads();

    float e[4];
    int c = 0;
    float ps = 0.f;
    for (int j = tid; j < n; j += 256) {
        float v = __expf(Sr[j] - m);
        e[c++] = v;
        ps += v;
    }
    #pragma unroll
    for (int o = 16; o; o >>= 1) ps += __shfl_xor_sync(0xffffffffu, ps, o);
    if (lane == 0) red[wid] = ps;
    __syncthreads();
    if (tid == 0) {
        float s = 0.f;
        #pragma unroll
        for (int k = 0; k < 8; k++) s += red[k];
        red[0] = s;
    }
    __syncthreads();
    const float inv = 1.0f / red[0];

    c = 0;
    for (int j = tid; j < n; j += 256) {
        unsigned short hh, ll;
        split1(e[c++] * inv, hh, ll);
        PH[j] = __ushort_as_bfloat16(hh);
        PL[j] = __ushort_as_bfloat16(ll);
    }
    for (int j = tid; j < L_; j += 256)
        if (j >= n) { PH[j] = __ushort_as_bfloat16(0); PL[j] = __ushort_as_bfloat16(0); }
}

// ============================================================================
// PV mma: EXACT R8 known-good version (scalar fragment loads)
// ============================================================================
#define PROWP 72
#define PTILE_H (128 * PROWP)
#define PSTAGE_H (4 * PTILE_H)
#define SMEM_PV_BYTES (2 * PSTAGE_H * 2)      // 147456

__device__ __forceinline__ void pv_load_stage(
    u32 sbase, int s, int bh, int i0, int k0, int tid,
    const __nv_bfloat16* __restrict__ Phi, const __nv_bfloat16* __restrict__ Plo,
    const __nv_bfloat16* __restrict__ Vthi, const __nv_bfloat16* __restrict__ Vtlo)
{
    u32 st = sbase + (u32)s * (PSTAGE_H * 2);
    #pragma unroll
    for (int i = 0; i < 4; ++i) {
        int id = tid + i * 256;
        int r = id >> 3, sg = id & 7;
        u32 doff = (u32)(r * PROWP + sg * 8) * 2;
        u64 po = ((u64)bh * L_ + i0 + r) * L_ + k0 + sg * 8;
        u64 vo = ((u64)bh * D_ + r) * L_ + k0 + sg * 8;
        cp16(st + doff, Phi + po);
        cp16(st + PTILE_H * 2 + doff, Plo + po);
        cp16(st + PTILE_H * 4 + doff, Vthi + vo);
        cp16(st + PTILE_H * 6 + doff, Vtlo + vo);
    }
    asm volatile("cp.async.commit_group;" ::: "memory");
}

__global__ __launch_bounds__(256) void pv_mma_kernel(
    const __nv_bfloat16* __restrict__ Phi, const __nv_bfloat16* __restrict__ Plo,
    const __nv_bfloat16* __restrict__ Vthi, const __nv_bfloat16* __restrict__ Vtlo,
    float* __restrict__ O)
{
    extern __shared__ __align__(16) __nv_bfloat16 sh[];
    const int bh = blockIdx.z;
    const int i0 = blockIdx.y * 128;
    const int b = bh >> 4, h = bh & 15;
    const int tid = threadIdx.x;
    const int warp = tid >> 5, lane = tid & 31;
    const int wm = warp & 3, wn = warp >> 2;
    const u32 sbase = (u32)__cvta_generic_to_shared(sh);
    const int nch = 2 * (blockIdx.y + 1);

    float acc[2][8][4];
    #pragma unroll
    for (int i = 0; i < 2; i++)
        #pragma unroll
        for (int j = 0; j < 8; j++)
            #pragma unroll
            for (int k = 0; k < 4; k++) acc[i][j][k] = 0.f;

    pv_load_stage(sbase, 0, bh, i0, 0,  tid, Phi, Plo, Vthi, Vtlo);
    pv_load_stage(sbase, 1, bh, i0, 64, tid, Phi, Plo, Vthi, Vtlo);

    const int fr = lane >> 2;
    const int fc = (lane & 3) * 2;

    for (int c = 0; c < nch; ++c) {
        const int s = c & 1;
        if (c < nch - 1) asm volatile("cp.async.wait_group 1;" ::: "memory");
        else             asm volatile("cp.async.wait_group 0;" ::: "memory");
        __syncthreads();

        const __nv_bfloat16* sS = sh + s * PSTAGE_H;
        const __nv_bfloat16* aH = sS + (wm * 32 + fr) * PROWP + fc;
        const __nv_bfloat16* aL = aH + PTILE_H;
        const __nv_bfloat16* bH = sS + 2 * PTILE_H + (wn * 64 + fr) * PROWP + fc;
        const __nv_bfloat16* bL = bH + PTILE_H;

        #pragma unroll
        for (int kk = 0; kk < 64; kk += 16) {
            u32 fah[2][4], fal[2][4];
            #pragma unroll
            for (int mt = 0; mt < 2; ++mt) {
                const __nv_bfloat16* p = aH + mt * 16 * PROWP + kk;
                fah[mt][0] = *(const u32*)(p);
                fah[mt][1] = *(const u32*)(p + 8 * PROWP);
                fah[mt][2] = *(const u32*)(p + 8);
                fah[mt][3] = *(const u32*)(p + 8 * PROWP + 8);
                const __nv_bfloat16* q = aL + mt * 16 * PROWP + kk;
                fal[mt][0] = *(const u32*)(q);
                fal[mt][1] = *(const u32*)(q + 8 * PROWP);
                fal[mt][2] = *(const u32*)(q + 8);
                fal[mt][3] = *(const u32*)(q + 8 * PROWP + 8);
            }
            #pragma unroll
            for (int nt = 0; nt < 8; ++nt) {
                u32 fbh[2], fbl[2];
                const __nv_bfloat16* p = bH + nt * 8 * PROWP + kk;
                fbh[0] = *(const u32*)(p);
                fbh[1] = *(const u32*)(p + 8);
                const __nv_bfloat16* q = bL + nt * 8 * PROWP + kk;
                fbl[0] = *(const u32*)(q);
                fbl[1] = *(const u32*)(q + 8);
                #pragma unroll
                for (int mt = 0; mt < 2; ++mt) {
                    mma_bf16(acc[mt][nt], fah[mt], fbh);
                    mma_bf16(acc[mt][nt], fah[mt], fbl);
                    mma_bf16(acc[mt][nt], fal[mt], fbh);
                }
            }
        }
        __syncthreads();
        if (c + 2 < nch)
            pv_load_stage(sbase, s, bh, i0, (c + 2) * 64, tid, Phi, Plo, Vthi, Vtlo);
    }

    #pragma unroll
    for (int mt = 0; mt < 2; ++mt) {
        #pragma unroll
        for (int nt = 0; nt < 8; ++nt) {
            int m = i0 + wm * 32 + mt * 16 + fr;
            int n = wn * 64 + nt * 8 + fc;
            float2 v0 = make_float2(acc[mt][nt][0], acc[mt][nt][1]);
            float2 v1 = make_float2(acc[mt][nt][2], acc[mt][nt][3]);
            *(float2*)(O + ((u64)(b * L_ + m) * E_) + h * D_ + n) = v0;
            *(float2*)(O + ((u64)(b * L_ + m + 8) * E_) + h * D_ + n) = v1;
        }
    }
}

// ============================================================================
// v-orthogonalization   (R8 known-good)
// ============================================================================
__global__ __launch_bounds__(256) void ortho_kernel(
    float* __restrict__ O, const float* __restrict__ V)
{
    int gw = blockIdx.x * 8 + (threadIdx.x >> 5);
    int lane = threadIdx.x & 31;
    int row = gw / H_;
    int h = gw % H_;
    float* o = O + (u64)row * E_ + h * D_;
    const float* v = V + (u64)row * E_ + h * D_;

    float ov[4], vv[4];
    #pragma unroll
    for (int k = 0; k < 4; k++) { ov[k] = o[lane + 32*k]; vv[k] = v[lane + 32*k]; }
    float ss = 0.f, sv = 0.f;
    #pragma unroll
    for (int k = 0; k < 4; k++) { ss = fmaf(vv[k], vv[k], ss); sv = fmaf(ov[k], vv[k], sv); }
    #pragma unroll
    for (int off = 16; off; off >>= 1) {
        ss += __shfl_xor_sync(0xffffffffu, ss, off);
        sv += __shfl_xor_sync(0xffffffffu, sv, off);
    }
    float vnorm = sqrtf(ss);
    float inv = 1.0f / fmaxf(vnorm, 1e-9f);
    float coef = sv * inv * inv;
    #pragma unroll
    for (int k = 0; k < 4; k++) o[lane + 32*k] = ov[k] - coef * vv[k];
}

// ============================================================================
extern "C" void kernel_launch(void* const* d_in, const int* in_sizes, int n_in,
                              void* d_out, int out_size)
{
    const float* query = (const float*)d_in[0];
    const float* key   = (const float*)d_in[1];
    const float* value = (const float*)d_in[2];
    const float* cosp  = (const float*)d_in[4];
    const float* sinp  = (const float*)d_in[5];
    const float* Wq = (const float*)d_in[6];
    const float* bq = (const float*)d_in[7];
    const float* Wk = (const float*)d_in[8];
    const float* bk = (const float*)d_in[9];
    const float* Wv = (const float*)d_in[10];
    const float* bv = (const float*)d_in[11];
    const float* Wo = (const float*)d_in[12];
    const float* bo = (const float*)d_in[13];
    float* out = (float*)d_out;

    float *gQ, *gK, *gV, *gO, *gS;
    __nv_bfloat16 *gAhi, *gAlo, *gWhi, *gWlo;
    __nv_bfloat16 *gQhi, *gQlo, *gKhi, *gKlo, *gVthi, *gVtlo, *gPhi, *gPlo;
    cudaGetSymbolAddress((void**)&gQ, g_Q);
    cudaGetSymbolAddress((void**)&gK, g_K);
    cudaGetSymbolAddress((void**)&gV, g_V);
    cudaGetSymbolAddress((void**)&gO, g_O);
    cudaGetSymbolAddress((void**)&gS, g_S);
    cudaGetSymbolAddress((void**)&gAhi, g_Ahi);
    cudaGetSymbolAddress((void**)&gAlo, g_Alo);
    cudaGetSymbolAddress((void**)&gWhi, g_Whi);
    cudaGetSymbolAddress((void**)&gWlo, g_Wlo);
    cudaGetSymbolAddress((void**)&gQhi, g_Qhi);
    cudaGetSymbolAddress((void**)&gQlo, g_Qlo);
    cudaGetSymbolAddress((void**)&gKhi, g_Khi);
    cudaGetSymbolAddress((void**)&gKlo, g_Klo);
    cudaGetSymbolAddress((void**)&gVthi, g_Vthi);
    cudaGetSymbolAddress((void**)&gVtlo, g_Vtlo);
    cudaGetSymbolAddress((void**)&gPhi, g_Phi);
    cudaGetSymbolAddress((void**)&gPlo, g_Plo);

    cudaFuncSetAttribute(gemm_mma_kernel, cudaFuncAttributeMaxDynamicSharedMemorySize,
                         SMEM_GEMM_BYTES);
    cudaFuncSetAttribute(scores_mma_kernel, cudaFuncAttributeMaxDynamicSharedMemorySize,
                         SMEM_SC_BYTES);
    cudaFuncSetAttribute(pv_mma_kernel, cudaFuncAttributeMaxDynamicSharedMemorySize,
                         SMEM_PV_BYTES);

    const dim3 blk(256);
    const int nAct = BL_ * E_;
    const int nW   = E_ * E_;
    const dim3 gGemm(GM_N / 128, GM_M / 128);

    // Q projection
    split_kernel<<<nAct / 1024, blk>>>(query, gAhi, gAlo, nAct);
    split_kernel<<<nW / 1024, blk>>>(Wq, gWhi, gWlo, nW);
    gemm_mma_kernel<<<gGemm, blk, SMEM_GEMM_BYTES>>>(gAhi, gAlo, gWhi, gWlo, bq, gQ);
    // K projection
    split_kernel<<<nAct / 1024, blk>>>(key, gAhi, gAlo, nAct);
    split_kernel<<<nW / 1024, blk>>>(Wk, gWhi, gWlo, nW);
    gemm_mma_kernel<<<gGemm, blk, SMEM_GEMM_BYTES>>>(gAhi, gAlo, gWhi, gWlo, bk, gK);
    // V projection
    split_kernel<<<nAct / 1024, blk>>>(value, gAhi, gAlo, nAct);
    split_kernel<<<nW / 1024, blk>>>(Wv, gWhi, gWlo, nW);
    gemm_mma_kernel<<<gGemm, blk, SMEM_GEMM_BYTES>>>(gAhi, gAlo, gWhi, gWlo, bv, gV);

    normrope_kernel<<<(2 * BL_ * H_) / 8, blk>>>(gQ, gK, gQhi, gQlo, gKhi, gKlo, cosp, sinp);
    vsplit_kernel<<<dim3(BH_, L_ / 32), blk>>>(gV, gVthi, gVtlo);

    scores_mma_kernel<<<dim3(L_ / 128, L_ / 128, BH_), blk, SMEM_SC_BYTES>>>(
        gQhi, gQlo, gKhi, gKlo, gS);
    softmax_kernel<<<BH_ * L_, blk>>>(gS, gPhi, gPlo);
    pv_mma_kernel<<<dim3(1, L_ / 128, BH_), blk, SMEM_PV_BYTES>>>(
        gPhi, gPlo, gVthi, gVtlo, gO);
    ortho_kernel<<<(BL_ * H_) / 8, blk>>>(gO, gV);

    // Output projection
    split_kernel<<<nAct / 1024, blk>>>(gO, gAhi, gAlo, nAct);
    split_kernel<<<nW / 1024, blk>>>(Wo, gWhi, gWlo, nW);
    gemm_mma_kernel<<<gGemm, blk, SMEM_GEMM_BYTES>>>(gAhi, gAlo, gWhi, gWlo, bo, out);
}

// round 17
// speedup vs baseline: 1.1753x; 1.1753x over previous
#include <cuda_runtime.h>
#include <cuda_bf16.h>
#include <cstdint>
#include <math.h>

typedef unsigned int u32;
typedef unsigned long long u64;

// Problem constants
#define B_  4
#define L_  1024
#define E_  2048
#define H_  16
#define D_  128
#define BL_ (B_*L_)            // 4096
#define BH_ (B_*H_)            // 64
#define SCALE_ 0.08838834764831845f   // 1/sqrt(128)

// -------- scratch (device globals; no allocation allowed) --------
__device__ float g_Q[(u64)BL_*E_];
__device__ float g_K[(u64)BL_*E_];
__device__ float g_V[(u64)BL_*E_];
__device__ float g_O[(u64)BL_*E_];
__device__ __nv_bfloat16 g_Ahi[(u64)BL_*E_];
__device__ __nv_bfloat16 g_Alo[(u64)BL_*E_];
__device__ __nv_bfloat16 g_Whi[(u64)E_*E_];
__device__ __nv_bfloat16 g_Wlo[(u64)E_*E_];
__device__ __nv_bfloat16 g_Qhi[(u64)BH_*L_*D_];  // [bh][l][d]
__device__ __nv_bfloat16 g_Qlo[(u64)BH_*L_*D_];
__device__ __nv_bfloat16 g_Khi[(u64)BH_*L_*D_];
__device__ __nv_bfloat16 g_Klo[(u64)BH_*L_*D_];
__device__ __nv_bfloat16 g_Vthi[(u64)BH_*D_*L_]; // [bh][d][l]
__device__ __nv_bfloat16 g_Vtlo[(u64)BH_*D_*L_];

// ============================================================================
// helpers
// ============================================================================
__device__ __forceinline__ void cp16(u32 dst, const void* src) {
    asm volatile("cp.async.cg.shared.global [%0], [%1], 16;" :: "r"(dst), "l"(src) : "memory");
}

__device__ __forceinline__ void mma_bf16(float* d, const u32* a, const u32* b) {
    asm volatile(
        "mma.sync.aligned.m16n8k16.row.col.f32.bf16.bf16.f32 "
        "{%0,%1,%2,%3}, {%4,%5,%6,%7}, {%8,%9}, {%0,%1,%2,%3};"
        : "+f"(d[0]), "+f"(d[1]), "+f"(d[2]), "+f"(d[3])
        : "r"(a[0]), "r"(a[1]), "r"(a[2]), "r"(a[3]), "r"(b[0]), "r"(b[1]));
}

__device__ __forceinline__ void split1(float v, unsigned short& h, unsigned short& l) {
    __nv_bfloat16 hb = __float2bfloat16(v);
    __nv_bfloat16 lb = __float2bfloat16(v - __bfloat162float(hb));
    h = __bfloat16_as_ushort(hb);
    l = __bfloat16_as_ushort(lb);
}

__device__ __forceinline__ u32 pack2bf(float a, float b) {
    unsigned short x = __bfloat16_as_ushort(__float2bfloat16(a));
    unsigned short y = __bfloat16_as_ushort(__float2bfloat16(b));
    return (u32)x | ((u32)y << 16);
}
__device__ __forceinline__ u32 pack2bf_lo(float a, float b) {
    __nv_bfloat16 ah = __float2bfloat16(a);
    __nv_bfloat16 bh = __float2bfloat16(b);
    unsigned short x = __bfloat16_as_ushort(__float2bfloat16(a - __bfloat162float(ah)));
    unsigned short y = __bfloat16_as_ushort(__float2bfloat16(b - __bfloat162float(bh)));
    return (u32)x | ((u32)y << 16);
}

// ============================================================================
// Split fp32 -> bf16 hi + bf16 lo
// ============================================================================
__global__ __launch_bounds__(256) void split_kernel(
    const float* __restrict__ X, __nv_bfloat16* __restrict__ hi,
    __nv_bfloat16* __restrict__ lo, int n)
{
    int i = (blockIdx.x * 256 + threadIdx.x) * 4;
    if (i >= n) return;
    float4 x = *(const float4*)(X + i);
    float v[4] = {x.x, x.y, x.z, x.w};
    unsigned short hv[4], lv[4];
    #pragma unroll
    for (int k = 0; k < 4; k++) split1(v[k], hv[k], lv[k]);
    *(ushort4*)(hi + i) = make_ushort4(hv[0], hv[1], hv[2], hv[3]);
    *(ushort4*)(lo + i) = make_ushort4(lv[0], lv[1], lv[2], lv[3]);
}

// ============================================================================
// Projection GEMM: EXACT R8 known-good version
// ============================================================================
#define GM_M 4096
#define GM_N 2048
#define GM_K 2048
#define BKH 32
#define ROWP 40
#define T_ALO_H 5120
#define T_BHI_H 10240
#define T_BLO_H 15360
#define STAGEH 20480
#define NCH (GM_K / BKH)
#define SMEM_GEMM_BYTES (2 * STAGEH * 2)   // 81920

__device__ __forceinline__ void g_load_stage(
    u32 sbase, int s, int m0, int n0, int k0, int tid,
    const __nv_bfloat16* __restrict__ Ahi, const __nv_bfloat16* __restrict__ Alo,
    const __nv_bfloat16* __restrict__ Bhi, const __nv_bfloat16* __restrict__ Blo)
{
    u32 st = sbase + (u32)s * (STAGEH * 2);
    #pragma unroll
    for (int i = 0; i < 2; ++i) {
        int id = tid + i * 256;
        int r = id >> 2, sg = id & 3;
        u32 doff = (u32)(r * ROWP + sg * 8) * 2;
        u64 ao = (u64)(m0 + r) * GM_K + k0 + sg * 8;
        u64 bo = (u64)(n0 + r) * GM_K + k0 + sg * 8;
        cp16(st + doff, Ahi + ao);
        cp16(st + T_ALO_H * 2 + doff, Alo + ao);
        cp16(st + T_BHI_H * 2 + doff, Bhi + bo);
        cp16(st + T_BLO_H * 2 + doff, Blo + bo);
    }
    asm volatile("cp.async.commit_group;" ::: "memory");
}

__global__ __launch_bounds__(256) void gemm_mma_kernel(
    const __nv_bfloat16* __restrict__ Ahi, const __nv_bfloat16* __restrict__ Alo,
    const __nv_bfloat16* __restrict__ Bhi, const __nv_bfloat16* __restrict__ Blo,
    const float* __restrict__ bias, float* __restrict__ C)
{
    extern __shared__ __align__(16) __nv_bfloat16 sh[];
    const int tid = threadIdx.x;
    const int m0 = blockIdx.y * 128;
    const int n0 = blockIdx.x * 128;
    const int warp = tid >> 5, lane = tid & 31;
    const int wm = warp & 3, wn = warp >> 2;
    const u32 sbase = (u32)__cvta_generic_to_shared(sh);

    float acc[2][8][4];
    #pragma unroll
    for (int i = 0; i < 2; i++)
        #pragma unroll
        for (int j = 0; j < 8; j++)
            #pragma unroll
            for (int k = 0; k < 4; k++) acc[i][j][k] = 0.f;

    g_load_stage(sbase, 0, m0, n0, 0,   tid, Ahi, Alo, Bhi, Blo);
    g_load_stage(sbase, 1, m0, n0, BKH, tid, Ahi, Alo, Bhi, Blo);

    const int fr = lane >> 2;
    const int fc = (lane & 3) * 2;

    for (int c = 0; c < NCH; ++c) {
        const int s = c & 1;
        if (c < NCH - 1) asm volatile("cp.async.wait_group 1;" ::: "memory");
        else             asm volatile("cp.async.wait_group 0;" ::: "memory");
        __syncthreads();

        const __nv_bfloat16* sS = sh + s * STAGEH;
        const __nv_bfloat16* aH = sS + (wm * 32 + fr) * ROWP + fc;
        const __nv_bfloat16* aL = aH + T_ALO_H;
        const __nv_bfloat16* bH = sS + T_BHI_H + (wn * 64 + fr) * ROWP + fc;
        const __nv_bfloat16* bL = bH + (T_BLO_H - T_BHI_H);

        #pragma unroll
        for (int kk = 0; kk < BKH; kk += 16) {
            u32 fah[2][4], fal[2][4];
            #pragma unroll
            for (int mt = 0; mt < 2; ++mt) {
                const __nv_bfloat16* p = aH + mt * 16 * ROWP + kk;
                fah[mt][0] = *(const u32*)(p);
                fah[mt][1] = *(const u32*)(p + 8 * ROWP);
                fah[mt][2] = *(const u32*)(p + 8);
                fah[mt][3] = *(const u32*)(p + 8 * ROWP + 8);
                const __nv_bfloat16* q = aL + mt * 16 * ROWP + kk;
                fal[mt][0] = *(const u32*)(q);
                fal[mt][1] = *(const u32*)(q + 8 * ROWP);
                fal[mt][2] = *(const u32*)(q + 8);
                fal[mt][3] = *(const u32*)(q + 8 * ROWP + 8);
            }
            #pragma unroll
            for (int nt = 0; nt < 8; ++nt) {
                u32 fbh[2], fbl[2];
                const __nv_bfloat16* p = bH + nt * 8 * ROWP + kk;
                fbh[0] = *(const u32*)(p);
                fbh[1] = *(const u32*)(p + 8);
                const __nv_bfloat16* q = bL + nt * 8 * ROWP + kk;
                fbl[0] = *(const u32*)(q);
                fbl[1] = *(const u32*)(q + 8);
                #pragma unroll
                for (int mt = 0; mt < 2; ++mt) {
                    mma_bf16(acc[mt][nt], fah[mt], fbh);
                    mma_bf16(acc[mt][nt], fah[mt], fbl);
                    mma_bf16(acc[mt][nt], fal[mt], fbh);
                }
            }
        }
        __syncthreads();
        if (c + 2 < NCH)
            g_load_stage(sbase, s, m0, n0, (c + 2) * BKH, tid, Ahi, Alo, Bhi, Blo);
    }

    #pragma unroll
    for (int mt = 0; mt < 2; ++mt) {
        #pragma unroll
        for (int nt = 0; nt < 8; ++nt) {
            int m = m0 + wm * 32 + mt * 16 + fr;
            int n = n0 + wn * 64 + nt * 8 + fc;
            float b0 = bias[n], b1 = bias[n + 1];
            float2 v0 = make_float2(acc[mt][nt][0] + b0, acc[mt][nt][1] + b1);
            float2 v1 = make_float2(acc[mt][nt][2] + b0, acc[mt][nt][3] + b1);
            *(float2*)(C + (u64)m * GM_N + n) = v0;
            *(float2*)(C + (u64)(m + 8) * GM_N + n) = v1;
        }
    }
}

// ============================================================================
// RMSNorm + rotary -> bf16 hi/lo [bh][l][d]
// ============================================================================
__global__ __launch_bounds__(256) void normrope_kernel(
    const float* __restrict__ Q, const float* __restrict__ Kb,
    __nv_bfloat16* __restrict__ Qhi, __nv_bfloat16* __restrict__ Qlo,
    __nv_bfloat16* __restrict__ Khi, __nv_bfloat16* __restrict__ Klo,
    const float* __restrict__ cosp, const float* __restrict__ sinp)
{
    int gw = blockIdx.x * 8 + (threadIdx.x >> 5);
    int lane = threadIdx.x & 31;
    bool isQ = (gw < BL_ * H_);
    const float* X = isQ ? Q : Kb;
    __nv_bfloat16* OH = isQ ? Qhi : Khi;
    __nv_bfloat16* OL = isQ ? Qlo : Klo;
    int w = gw % (BL_ * H_);
    int row = w / H_;
    int h   = w % H_;
    int b   = row >> 10;
    int l   = row & (L_ - 1);
    const float* x = X + (u64)row * E_ + h * D_;

    float v0 = x[lane], v1 = x[lane+32], v2 = x[lane+64], v3 = x[lane+96];
    float ss = v0*v0 + v1*v1 + v2*v2 + v3*v3;
    #pragma unroll
    for (int o = 16; o; o >>= 1) ss += __shfl_xor_sync(0xffffffffu, ss, o);
    float r = rsqrtf(ss * (1.0f / 128.0f) + 1e-6f);
    v0 *= r; v1 *= r; v2 *= r; v3 *= r;

    float c0 = cosp[l*64 + lane],      s0 = sinp[l*64 + lane];
    float c1 = cosp[l*64 + lane + 32], s1 = sinp[l*64 + lane + 32];
    float y0 = v0 * c0 - v2 * s0;
    float y2 = v0 * s0 + v2 * c0;
    float y1 = v1 * c1 - v3 * s1;
    float y3 = v1 * s1 + v3 * c1;

    u64 base = ((u64)(b * H_ + h) * L_ + l) * D_;
    unsigned short hh, ll;
    split1(y0, hh, ll); OH[base + lane]      = __ushort_as_bfloat16(hh); OL[base + lane]      = __ushort_as_bfloat16(ll);
    split1(y1, hh, ll); OH[base + lane + 32] = __ushort_as_bfloat16(hh); OL[base + lane + 32] = __ushort_as_bfloat16(ll);
    split1(y2, hh, ll); OH[base + lane + 64] = __ushort_as_bfloat16(hh); OL[base + lane + 64] = __ushort_as_bfloat16(ll);
    split1(y3, hh, ll); OH[base + lane + 96] = __ushort_as_bfloat16(hh); OL[base + lane + 96] = __ushort_as_bfloat16(ll);
}

// ============================================================================
// V transpose+split -> [bh][d][l] hi/lo
// ============================================================================
__global__ __launch_bounds__(256) void vsplit_kernel(
    const float* __restrict__ V,
    __nv_bfloat16* __restrict__ Vthi, __nv_bfloat16* __restrict__ Vtlo)
{
    __shared__ float tile[32][132];
    const int bh = blockIdx.x;
    const int l0 = blockIdx.y * 32;
    const int b = bh >> 4, h = bh & 15;
    const int tid = threadIdx.x;

    #pragma unroll
    for (int i = 0; i < 16; ++i) {
        int id = tid + i * 256;
        int l = id >> 7, d = id & 127;
        tile[l][d] = V[((u64)(b * L_ + l0 + l)) * E_ + h * D_ + d];
    }
    __syncthreads();
    #pragma unroll
    for (int i = 0; i < 16; ++i) {
        int id = tid + i * 256;
        int d = id >> 5, l = id & 31;
        float v = tile[l][d];
        unsigned short hh, ll;
        split1(v, hh, ll);
        u64 o = ((u64)bh * D_ + d) * L_ + l0 + l;
        Vthi[o] = __ushort_as_bfloat16(hh);
        Vtlo[o] = __ushort_as_bfloat16(ll);
    }
}

// ============================================================================
// Fused flash attention. CTA = (bh, i-block 128). 8 warps; warp owns 16 i-rows
// and the FULL d=128 output (16 n-tiles).
// SMEM: Qhi,Qlo,Khi,Klo,Vhi,Vlo tiles of [128][136] halves.
// ============================================================================
#define FROWP 136
#define FTILE (128 * FROWP)                  // 17408 halves
#define SMEM_FA_BYTES (6 * FTILE * 2)        // 208896

__global__ __launch_bounds__(256) void flash_kernel(
    const __nv_bfloat16* __restrict__ Qhi, const __nv_bfloat16* __restrict__ Qlo,
    const __nv_bfloat16* __restrict__ Khi, const __nv_bfloat16* __restrict__ Klo,
    const __nv_bfloat16* __restrict__ Vthi, const __nv_bfloat16* __restrict__ Vtlo,
    float* __restrict__ O)
{
    extern __shared__ __align__(16) __nv_bfloat16 sh[];
    const int bh = blockIdx.x;
    const int ib = 7 - (int)blockIdx.y;          // heavy blocks first
    const int i0 = ib * 128;
    const int b = bh >> 4, h = bh & 15;
    const int tid = threadIdx.x;
    const int warp = tid >> 5, lane = tid & 31;
    const int fr = lane >> 2, fc = (lane & 3) * 2;
    const u32 sbase = (u32)__cvta_generic_to_shared(sh);

    // load Q tile (hi at 0, lo at FTILE)
    #pragma unroll
    for (int i = 0; i < 8; ++i) {
        int id = tid + i * 256;
        int r = id >> 4, sg = id & 15;
        u32 doff = (u32)(r * FROWP + sg * 8) * 2;
        u64 qo = ((u64)bh * L_ + i0 + r) * D_ + sg * 8;
        cp16(sbase + doff, Qhi + qo);
        cp16(sbase + FTILE * 2 + doff, Qlo + qo);
    }
    asm volatile("cp.async.commit_group;" ::: "memory");

    float o[16][4];
    #pragma unroll
    for (int d = 0; d < 16; d++)
        #pragma unroll
        for (int k = 0; k < 4; k++) o[d][k] = 0.f;
    float mrun0 = -3.0e38f, mrun1 = -3.0e38f, lrun0 = 0.f, lrun1 = 0.f;

    const int njb = ib + 1;
    for (int jc = 0; jc < njb; ++jc) {
        const int j0 = jc * 128;
        // load K (2F,3F) and Vt (4F,5F) tiles
        #pragma unroll
        for (int i = 0; i < 8; ++i) {
            int id = tid + i * 256;
            int r = id >> 4, sg = id & 15;
            u32 doff = (u32)(r * FROWP + sg * 8) * 2;
            u64 ko = ((u64)bh * L_ + j0 + r) * D_ + sg * 8;
            u64 vo = ((u64)bh * D_ + r) * L_ + j0 + sg * 8;
            cp16(sbase + FTILE * 4 + doff, Khi + ko);
            cp16(sbase + FTILE * 6 + doff, Klo + ko);
            cp16(sbase + FTILE * 8 + doff, Vthi + vo);
            cp16(sbase + FTILE * 10 + doff, Vtlo + vo);
        }
        asm volatile("cp.async.commit_group;" ::: "memory");
        asm volatile("cp.async.wait_group 0;" ::: "memory");
        __syncthreads();

        // ---- S = Q K^T (warp: 16 rows x 128 cols = 16 n-tiles) ----
        float s[16][4];
        #pragma unroll
        for (int nt = 0; nt < 16; nt++)
            #pragma unroll
            for (int k = 0; k < 4; k++) s[nt][k] = 0.f;

        const __nv_bfloat16* aHp = sh + (warp * 16 + fr) * FROWP + fc;
        const __nv_bfloat16* aLp = aHp + FTILE;
        const __nv_bfloat16* bHp = sh + 2 * FTILE + fr * FROWP + fc;
        const __nv_bfloat16* bLp = bHp + FTILE;

        #pragma unroll
        for (int kk = 0; kk < 128; kk += 16) {
            u32 ah[4], al[4];
            ah[0] = *(const u32*)(aHp + kk);
            ah[1] = *(const u32*)(aHp + 8 * FROWP + kk);
            ah[2] = *(const u32*)(aHp + kk + 8);
            ah[3] = *(const u32*)(aHp + 8 * FROWP + kk + 8);
            al[0] = *(const u32*)(aLp + kk);
            al[1] = *(const u32*)(aLp + 8 * FROWP + kk);
            al[2] = *(const u32*)(aLp + kk + 8);
            al[3] = *(const u32*)(aLp + 8 * FROWP + kk + 8);
            #pragma unroll
            for (int nt = 0; nt < 16; ++nt) {
                u32 fbh[2], fbl[2];
                const __nv_bfloat16* p = bHp + nt * 8 * FROWP + kk;
                fbh[0] = *(const u32*)(p);
                fbh[1] = *(const u32*)(p + 8);
                const __nv_bfloat16* q = bLp + nt * 8 * FROWP + kk;
                fbl[0] = *(const u32*)(q);
                fbl[1] = *(const u32*)(q + 8);
                mma_bf16(s[nt], ah, fbh);
                mma_bf16(s[nt], ah, fbl);
                mma_bf16(s[nt], al, fbh);
            }
        }

        // scale + causal mask (diagonal block only)
        #pragma unroll
        for (int nt = 0; nt < 16; nt++)
            #pragma unroll
            for (int k = 0; k < 4; k++) s[nt][k] *= SCALE_;
        if (j0 == i0) {
            const int ir0 = i0 + warp * 16 + fr;
            const int ir1 = ir0 + 8;
            #pragma unroll
            for (int nt = 0; nt < 16; nt++) {
                int jcol = j0 + nt * 8 + fc;
                if (jcol     > ir0) s[nt][0] = -1e30f;
                if (jcol + 1 > ir0) s[nt][1] = -1e30f;
                if (jcol     > ir1) s[nt][2] = -1e30f;
                if (jcol + 1 > ir1) s[nt][3] = -1e30f;
            }
        }

        // online softmax (rows fr and fr+8 of this warp's 16-row group)
        float m0 = -3.0e38f, m1 = -3.0e38f;
        #pragma unroll
        for (int nt = 0; nt < 16; nt++) {
            m0 = fmaxf(m0, fmaxf(s[nt][0], s[nt][1]));
            m1 = fmaxf(m1, fmaxf(s[nt][2], s[nt][3]));
        }
        m0 = fmaxf(m0, __shfl_xor_sync(0xffffffffu, m0, 1));
        m0 = fmaxf(m0, __shfl_xor_sync(0xffffffffu, m0, 2));
        m1 = fmaxf(m1, __shfl_xor_sync(0xffffffffu, m1, 1));
        m1 = fmaxf(m1, __shfl_xor_sync(0xffffffffu, m1, 2));
        float mn0 = fmaxf(mrun0, m0), mn1 = fmaxf(mrun1, m1);
        float a0 = __expf(mrun0 - mn0), a1 = __expf(mrun1 - mn1);
        #pragma unroll
        for (int d = 0; d < 16; d++) {
            o[d][0] *= a0; o[d][1] *= a0;
            o[d][2] *= a1; o[d][3] *= a1;
        }
        float r0 = 0.f, r1 = 0.f;
        #pragma unroll
        for (int nt = 0; nt < 16; nt++) {
            s[nt][0] = __expf(s[nt][0] - mn0); r0 += s[nt][0];
            s[nt][1] = __expf(s[nt][1] - mn0); r0 += s[nt][1];
            s[nt][2] = __expf(s[nt][2] - mn1); r1 += s[nt][2];
            s[nt][3] = __expf(s[nt][3] - mn1); r1 += s[nt][3];
        }
        r0 += __shfl_xor_sync(0xffffffffu, r0, 1);
        r0 += __shfl_xor_sync(0xffffffffu, r0, 2);
        r1 += __shfl_xor_sync(0xffffffffu, r1, 1);
        r1 += __shfl_xor_sync(0xffffffffu, r1, 2);
        lrun0 = lrun0 * a0 + r0;
        lrun1 = lrun1 * a1 + r1;
        mrun0 = mn0; mrun1 = mn1;

        // ---- O += P V : 8 k-tiles (j) x 16 d-tiles ----
        const __nv_bfloat16* vHp = sh + 4 * FTILE + fr * FROWP + fc;
        const __nv_bfloat16* vLp = vHp + FTILE;
        #pragma unroll
        for (int kt = 0; kt < 8; ++kt) {
            u32 pah[4], pal[4];
            pah[0] = pack2bf(s[2*kt][0],   s[2*kt][1]);
            pah[1] = pack2bf(s[2*kt][2],   s[2*kt][3]);
            pah[2] = pack2bf(s[2*kt+1][0], s[2*kt+1][1]);
            pah[3] = pack2bf(s[2*kt+1][2], s[2*kt+1][3]);
            pal[0] = pack2bf_lo(s[2*kt][0],   s[2*kt][1]);
            pal[1] = pack2bf_lo(s[2*kt][2],   s[2*kt][3]);
            pal[2] = pack2bf_lo(s[2*kt+1][0], s[2*kt+1][1]);
            pal[3] = pack2bf_lo(s[2*kt+1][2], s[2*kt+1][3]);
            #pragma unroll
            for (int dt = 0; dt < 16; ++dt) {
                u32 fbh[2], fbl[2];
                const __nv_bfloat16* p = vHp + dt * 8 * FROWP + kt * 16;
                fbh[0] = *(const u32*)(p);
                fbh[1] = *(const u32*)(p + 8);
                const __nv_bfloat16* q = vLp + dt * 8 * FROWP + kt * 16;
                fbl[0] = *(const u32*)(q);
                fbl[1] = *(const u32*)(q + 8);
                mma_bf16(o[dt], pah, fbh);
                mma_bf16(o[dt], pah, fbl);
                mma_bf16(o[dt], pal, fbh);
            }
        }
        __syncthreads();   // before next iteration overwrites K/V tiles
    }

    const float inv0 = 1.0f / lrun0, inv1 = 1.0f / lrun1;
    const int m = i0 + warp * 16 + fr;
    #pragma unroll
    for (int dt = 0; dt < 16; ++dt) {
        int n = dt * 8 + fc;
        float2 v0 = make_float2(o[dt][0] * inv0, o[dt][1] * inv0);
        float2 v1 = make_float2(o[dt][2] * inv1, o[dt][3] * inv1);
        *(float2*)(O + (u64)(b * L_ + m) * E_ + h * D_ + n) = v0;
        *(float2*)(O + (u64)(b * L_ + m + 8) * E_ + h * D_ + n) = v1;
    }
}

// ============================================================================
// v-orthogonalization
// ============================================================================
__global__ __launch_bounds__(256) void ortho_kernel(
    float* __restrict__ O, const float* __restrict__ V)
{
    int gw = blockIdx.x * 8 + (threadIdx.x >> 5);
    int lane = threadIdx.x & 31;
    int row = gw / H_;
    int h = gw % H_;
    float* o = O + (u64)row * E_ + h * D_;
    const float* v = V + (u64)row * E_ + h * D_;

    float ov[4], vv[4];
    #pragma unroll
    for (int k = 0; k < 4; k++) { ov[k] = o[lane + 32*k]; vv[k] = v[lane + 32*k]; }
    float ss = 0.f, sv = 0.f;
    #pragma unroll
    for (int k = 0; k < 4; k++) { ss = fmaf(vv[k], vv[k], ss); sv = fmaf(ov[k], vv[k], sv); }
    #pragma unroll
    for (int off = 16; off; off >>= 1) {
        ss += __shfl_xor_sync(0xffffffffu, ss, off);
        sv += __shfl_xor_sync(0xffffffffu, sv, off);
    }
    float vnorm = sqrtf(ss);
    float inv = 1.0f / fmaxf(vnorm, 1e-9f);
    float coef = sv * inv * inv;
    #pragma unroll
    for (int k = 0; k < 4; k++) o[lane + 32*k] = ov[k] - coef * vv[k];
}

// ============================================================================
extern "C" void kernel_launch(void* const* d_in, const int* in_sizes, int n_in,
                              void* d_out, int out_size)
{
    const float* query = (const float*)d_in[0];
    const float* key   = (const float*)d_in[1];
    const float* value = (const float*)d_in[2];
    const float* cosp  = (const float*)d_in[4];
    const float* sinp  = (const float*)d_in[5];
    const float* Wq = (const float*)d_in[6];
    const float* bq = (const float*)d_in[7];
    const float* Wk = (const float*)d_in[8];
    const float* bk = (const float*)d_in[9];
    const float* Wv = (const float*)d_in[10];
    const float* bv = (const float*)d_in[11];
    const float* Wo = (const float*)d_in[12];
    const float* bo = (const float*)d_in[13];
    float* out = (float*)d_out;

    float *gQ, *gK, *gV, *gO;
    __nv_bfloat16 *gAhi, *gAlo, *gWhi, *gWlo;
    __nv_bfloat16 *gQhi, *gQlo, *gKhi, *gKlo, *gVthi, *gVtlo;
    cudaGetSymbolAddress((void**)&gQ, g_Q);
    cudaGetSymbolAddress((void**)&gK, g_K);
    cudaGetSymbolAddress((void**)&gV, g_V);
    cudaGetSymbolAddress((void**)&gO, g_O);
    cudaGetSymbolAddress((void**)&gAhi, g_Ahi);
    cudaGetSymbolAddress((void**)&gAlo, g_Alo);
    cudaGetSymbolAddress((void**)&gWhi, g_Whi);
    cudaGetSymbolAddress((void**)&gWlo, g_Wlo);
    cudaGetSymbolAddress((void**)&gQhi, g_Qhi);
    cudaGetSymbolAddress((void**)&gQlo, g_Qlo);
    cudaGetSymbolAddress((void**)&gKhi, g_Khi);
    cudaGetSymbolAddress((void**)&gKlo, g_Klo);
    cudaGetSymbolAddress((void**)&gVthi, g_Vthi);
    cudaGetSymbolAddress((void**)&gVtlo, g_Vtlo);

    cudaFuncSetAttribute(gemm_mma_kernel, cudaFuncAttributeMaxDynamicSharedMemorySize,
                         SMEM_GEMM_BYTES);
    cudaFuncSetAttribute(flash_kernel, cudaFuncAttributeMaxDynamicSharedMemorySize,
                         SMEM_FA_BYTES);

    const dim3 blk(256);
    const int nAct = BL_ * E_;
    const int nW   = E_ * E_;
    const dim3 gGemm(GM_N / 128, GM_M / 128);

    // Q projection
    split_kernel<<<nAct / 1024, blk>>>(query, gAhi, gAlo, nAct);
    split_kernel<<<nW / 1024, blk>>>(Wq, gWhi, gWlo, nW);
    gemm_mma_kernel<<<gGemm, blk, SMEM_GEMM_BYTES>>>(gAhi, gAlo, gWhi, gWlo, bq, gQ);
    // K projection
    split_kernel<<<nAct / 1024, blk>>>(key, gAhi, gAlo, nAct);
    split_kernel<<<nW / 1024, blk>>>(Wk, gWhi, gWlo, nW);
    gemm_mma_kernel<<<gGemm, blk, SMEM_GEMM_BYTES>>>(gAhi, gAlo, gWhi, gWlo, bk, gK);
    // V projection
    split_kernel<<<nAct / 1024, blk>>>(value, gAhi, gAlo, nAct);
    split_kernel<<<nW / 1024, blk>>>(Wv, gWhi, gWlo, nW);
    gemm_mma_kernel<<<gGemm, blk, SMEM_GEMM_BYTES>>>(gAhi, gAlo, gWhi, gWlo, bv, gV);

    normrope_kernel<<<(2 * BL_ * H_) / 8, blk>>>(gQ, gK, gQhi, gQlo, gKhi, gKlo, cosp, sinp);
    vsplit_kernel<<<dim3(BH_, L_ / 32), blk>>>(gV, gVthi, gVtlo);

    flash_kernel<<<dim3(BH_, L_ / 128), blk, SMEM_FA_BYTES>>>(
        gQhi, gQlo, gKhi, gKlo, gVthi, gVtlo, gO);

    ortho_kernel<<<(BL_ * H_) / 8, blk>>>(gO, gV);

    // Output projection
    split_kernel<<<nAct / 1024, blk>>>(gO, gAhi, gAlo, nAct);
    split_kernel<<<nW / 1024, blk>>>(Wo, gWhi, gWlo, nW);
    gemm_mma_kernel<<<gGemm, blk, SMEM_GEMM_BYTES>>>(gAhi, gAlo, gWhi, gWlo, bo, out);
}